// round 6
// baseline (speedup 1.0000x reference)
#include <cuda_runtime.h>
#include <math.h>

// ---------------- problem constants ----------------
#define Bn   32
#define Ln   256
#define Dd   768
#define ATT  100
#define Hh   5
#define DK   20
#define NROW (Bn*Ln)            // 8192

// ---------------- scratch ----------------
#define OFF_G     6291456ll
#define OFF_Q     7110656ll
#define OFF_K     7929856ll
#define OFF_GO    8749056ll
#define OFF_HS0   11206656ll    // 32*256*256
#define OFF_HSW   13303808ll    // 32*256*256
#define OFF_ASP   23792768ll    // 32*20
#define OFF_SG1   23834368ll    // 8192
#define OFF_SG2   23875328ll
#define SCRATCH_TOTAL 23916288ll

__device__ __align__(16) float d_scratch[SCRATCH_TOTAL];

// =====================================================================
// 1. Fused LayerNorm + GEMM:  g = LN(x) @ Wxx_w + Wxx_b
//    grid NROW/32 = 256, 320 threads. BM=32, BN=100, BK=16, K=768.
// =====================================================================
__global__ __launch_bounds__(320, 3)
void lng_kernel(const float* __restrict__ x,
                const float* __restrict__ ga,
                const float* __restrict__ gb,
                const float* __restrict__ Ww,
                const float* __restrict__ Wb,
                float* __restrict__ g) {
    __shared__ __align__(16) float As[2][16][36];
    __shared__ __align__(16) float Bs[2][16][104];
    __shared__ float smean[32], sinv[32];

    int tid = threadIdx.x;
    int m0 = blockIdx.x * 32;
    int w = tid >> 5, lane = tid & 31;

    // ---- LN stats: warps 0..7, 4 rows each ----
    if (w < 8) {
        #pragma unroll
        for (int r = 0; r < 4; r++) {
            int row = w * 4 + r;
            const float4* xr = reinterpret_cast<const float4*>(x + (long long)(m0 + row) * Dd);
            float sum = 0.f, sq = 0.f;
            #pragma unroll
            for (int i = 0; i < 6; i++) {
                float4 v = xr[lane + i * 32];
                sum += v.x + v.y + v.z + v.w;
                sq  += v.x*v.x + v.y*v.y + v.z*v.z + v.w*v.w;
            }
            #pragma unroll
            for (int o = 16; o > 0; o >>= 1) {
                sum += __shfl_xor_sync(0xffffffffu, sum, o);
                sq  += __shfl_xor_sync(0xffffffffu, sq,  o);
            }
            if (lane == 0) {
                float mean = sum * (1.f / (float)Dd);
                float var = (sq - (float)Dd * mean * mean) * (1.f / (float)(Dd - 1));
                smean[row] = mean;
                sinv[row] = 1.f / (sqrtf(var) + 1e-6f);
            }
        }
    }
    __syncthreads();

    int tx = tid % 20, ty = tid / 20;     // ty 0..15 -> 2 rows each
    int tx5 = tx * 5, ty2 = ty * 2;

    bool aok = (tid < 128);
    int ar = tid >> 2, ac = (tid & 3) << 2;   // 32 rows x 16k /4
    int b0r = tid / 25, b0c = (tid % 25) * 4; // B tile 16x100 = 400 f4
    int bi1 = tid + 320;
    bool b1ok = (bi1 < 400);
    int b1r = bi1 / 25, b1c = (bi1 % 25) * 4;

    const float* Xrow = x + (long long)(m0 + ar) * Dd;
    float meanv = 0.f, invv = 0.f;
    if (aok) { meanv = smean[ar]; invv = sinv[ar]; }

    float acc[2][5];
    #pragma unroll
    for (int i = 0; i < 2; i++)
        #pragma unroll
        for (int j = 0; j < 5; j++) acc[i][j] = 0.f;

    float4 aR = make_float4(0.f,0.f,0.f,0.f), bR0 = aR, bR1 = aR;

    #define LOAD_LNA(k0)                                                 \
        do {                                                             \
            float4 x4 = *reinterpret_cast<const float4*>(Xrow + (k0) + ac);   \
            float4 ga4 = *reinterpret_cast<const float4*>(ga + (k0) + ac);    \
            float4 gb4 = *reinterpret_cast<const float4*>(gb + (k0) + ac);    \
            aR.x = ga4.x * (x4.x - meanv) * invv + gb4.x;                \
            aR.y = ga4.y * (x4.y - meanv) * invv + gb4.y;                \
            aR.z = ga4.z * (x4.z - meanv) * invv + gb4.z;                \
            aR.w = ga4.w * (x4.w - meanv) * invv + gb4.w;                \
        } while (0)

    if (aok) LOAD_LNA(0);
    bR0 = *reinterpret_cast<const float4*>(Ww + (long long)b0r * ATT + b0c);
    if (b1ok) bR1 = *reinterpret_cast<const float4*>(Ww + (long long)b1r * ATT + b1c);

    int s = 0;
    for (int t = 0; t < 48; t++) {
        if (aok) {
            As[s][ac + 0][ar] = aR.x;
            As[s][ac + 1][ar] = aR.y;
            As[s][ac + 2][ar] = aR.z;
            As[s][ac + 3][ar] = aR.w;
        }
        *reinterpret_cast<float4*>(&Bs[s][b0r][b0c]) = bR0;
        if (b1ok) *reinterpret_cast<float4*>(&Bs[s][b1r][b1c]) = bR1;
        __syncthreads();
        if (t + 1 < 48) {
            int k0 = (t + 1) * 16;
            if (aok) LOAD_LNA(k0);
            bR0 = *reinterpret_cast<const float4*>(Ww + (long long)(k0 + b0r) * ATT + b0c);
            if (b1ok) bR1 = *reinterpret_cast<const float4*>(Ww + (long long)(k0 + b1r) * ATT + b1c);
        }
        #pragma unroll
        for (int kk = 0; kk < 16; kk++) {
            float a0 = As[s][kk][ty2 + 0];
            float a1 = As[s][kk][ty2 + 1];
            float b0 = Bs[s][kk][tx5 + 0];
            float b1 = Bs[s][kk][tx5 + 1];
            float b2 = Bs[s][kk][tx5 + 2];
            float b3 = Bs[s][kk][tx5 + 3];
            float b4 = Bs[s][kk][tx5 + 4];
            acc[0][0] += a0*b0; acc[0][1] += a0*b1; acc[0][2] += a0*b2; acc[0][3] += a0*b3; acc[0][4] += a0*b4;
            acc[1][0] += a1*b0; acc[1][1] += a1*b1; acc[1][2] += a1*b2; acc[1][3] += a1*b3; acc[1][4] += a1*b4;
        }
        s ^= 1;
        __syncthreads();
    }
    #undef LOAD_LNA

    float wb[5];
    #pragma unroll
    for (int j = 0; j < 5; j++) wb[j] = Wb[tx5 + j];
    #pragma unroll
    for (int i = 0; i < 2; i++) {
        float* crow = g + (long long)(m0 + ty2 + i) * ATT;
        #pragma unroll
        for (int j = 0; j < 5; j++) crow[tx5 + j] = acc[i][j] + wb[j];
    }
}

// =====================================================================
// 2. Merged: q/k projections (GEMM K=100) + aspect pooling
// =====================================================================
__global__ __launch_bounds__(320, 2)
void qkaspect_kernel(const float* __restrict__ g,
                     const float* __restrict__ q_w, const float* __restrict__ q_b,
                     const float* __restrict__ k_w, const float* __restrict__ k_b,
                     const float* __restrict__ amask,
                     const float* __restrict__ dense_w,
                     const float* __restrict__ dense_b,
                     float* __restrict__ q, float* __restrict__ k,
                     float* __restrict__ asp) {
    int blk = blockIdx.x;
    int tid = threadIdx.x;

    if (blk < 256) {
        __shared__ __align__(16) float As[2][20][68];
        __shared__ __align__(16) float Bs[2][20][104];

        const float* Bw; const float* bias; float* C;
        if (blk < 128) { Bw = q_w; bias = q_b; C = q; }
        else           { Bw = k_w; bias = k_b; C = k; }
        int m0 = (blk & 127) * 64;

        int tx = tid % 20, ty = tid / 20;
        int tx5 = tx * 5, ty4 = ty * 4;

        int ar = tid / 5, ac = (tid % 5) * 4;
        int b0r = tid / 25, b0c = (tid % 25) * 4;
        int bi1 = tid + 320;
        bool b1ok = (bi1 < 500);
        int b1r = bi1 / 25, b1c = (bi1 % 25) * 4;

        const float* Arow = g + (long long)(m0 + ar) * ATT;

        float acc[4][5];
        #pragma unroll
        for (int i = 0; i < 4; i++)
            #pragma unroll
            for (int j = 0; j < 5; j++) acc[i][j] = 0.f;

        float4 aR, bR0, bR1 = make_float4(0.f,0.f,0.f,0.f);
        aR = *reinterpret_cast<const float4*>(Arow + ac);
        bR0 = *reinterpret_cast<const float4*>(Bw + (long long)b0r * ATT + b0c);
        if (b1ok) bR1 = *reinterpret_cast<const float4*>(Bw + (long long)b1r * ATT + b1c);

        int s = 0;
        for (int t = 0; t < 5; t++) {
            As[s][ac + 0][ar] = aR.x;
            As[s][ac + 1][ar] = aR.y;
            As[s][ac + 2][ar] = aR.z;
            As[s][ac + 3][ar] = aR.w;
            *reinterpret_cast<float4*>(&Bs[s][b0r][b0c]) = bR0;
            if (b1ok) *reinterpret_cast<float4*>(&Bs[s][b1r][b1c]) = bR1;
            __syncthreads();
            if (t + 1 < 5) {
                int k0 = (t + 1) * 20;
                aR = *reinterpret_cast<const float4*>(Arow + k0 + ac);
                bR0 = *reinterpret_cast<const float4*>(Bw + (long long)(k0 + b0r) * ATT + b0c);
                if (b1ok) bR1 = *reinterpret_cast<const float4*>(Bw + (long long)(k0 + b1r) * ATT + b1c);
            }
            #pragma unroll
            for (int kk = 0; kk < 20; kk++) {
                float4 a4 = *reinterpret_cast<const float4*>(&As[s][kk][ty4]);
                float b0 = Bs[s][kk][tx5 + 0];
                float b1 = Bs[s][kk][tx5 + 1];
                float b2 = Bs[s][kk][tx5 + 2];
                float b3 = Bs[s][kk][tx5 + 3];
                float b4 = Bs[s][kk][tx5 + 4];
                acc[0][0] += a4.x*b0; acc[0][1] += a4.x*b1; acc[0][2] += a4.x*b2; acc[0][3] += a4.x*b3; acc[0][4] += a4.x*b4;
                acc[1][0] += a4.y*b0; acc[1][1] += a4.y*b1; acc[1][2] += a4.y*b2; acc[1][3] += a4.y*b3; acc[1][4] += a4.y*b4;
                acc[2][0] += a4.z*b0; acc[2][1] += a4.z*b1; acc[2][2] += a4.z*b2; acc[2][3] += a4.z*b3; acc[2][4] += a4.z*b4;
                acc[3][0] += a4.w*b0; acc[3][1] += a4.w*b1; acc[3][2] += a4.w*b2; acc[3][3] += a4.w*b3; acc[3][4] += a4.w*b4;
            }
            s ^= 1;
            __syncthreads();
        }

        float wb[5];
        #pragma unroll
        for (int j = 0; j < 5; j++) wb[j] = bias[tx5 + j];
        #pragma unroll
        for (int i = 0; i < 4; i++) {
            float* crow = C + (long long)(m0 + ty4 + i) * ATT;
            #pragma unroll
            for (int j = 0; j < 5; j++) crow[tx5 + j] = acc[i][j] + wb[j];
        }
    } else {
        int b = blk - 256;
        int w = tid >> 5, lane = tid & 31;
        __shared__ float smask[Ln];
        __shared__ float part[8][104];
        __shared__ float sa[104];
        __shared__ float wred[8];

        if (tid < 256) smask[tid] = amask[b * Ln + tid];
        __syncthreads();

        if (w < 8) {
            float acc[4] = {0.f, 0.f, 0.f, 0.f};
            float wsum = 0.f;
            const float* gb_ = g + (long long)b * Ln * ATT;
            for (int i = w * 32; i < w * 32 + 32; i++) {
                float m = smask[i];
                wsum += m;
                const float* gr = gb_ + (long long)i * ATT;
                #pragma unroll
                for (int c4 = 0; c4 < 4; c4++) {
                    int c = lane + c4 * 32;
                    float gv = (c < ATT) ? gr[c] : 0.f;
                    acc[c4] += gv * m;
                }
            }
            #pragma unroll
            for (int c4 = 0; c4 < 4; c4++) {
                int c = lane + c4 * 32;
                if (c < ATT) part[w][c] = acc[c4];
            }
            if (lane == 0) wred[w] = wsum;
        }
        __syncthreads();
        if (tid < ATT) {
            float s = 0.f;
            #pragma unroll
            for (int ww = 0; ww < 8; ww++) s += part[ww][tid];
            sa[tid] = s;
        }
        if (tid == 0) {
            float s = 0.f;
            #pragma unroll
            for (int ww = 0; ww < 8; ww++) s += wred[ww];
            wred[0] = 1.f / s;
        }
        __syncthreads();
        float inv = wred[0];
        if (tid < DK) {
            float s = dense_b[tid];
            for (int c = 0; c < ATT; c++) s += sa[c] * inv * dense_w[c * DK + tid];
            asp[b * DK + tid] = s;
        }
    }
}

// =====================================================================
// 3. scores + aspsc + softmax, looped over h IN-BLOCK; adj never stored.
//    Outputs: hs0 = 0.2 * sum_h softmax_h  ;  hsw = sum_h softmax_h * wsum[h]
//    grid (Ln/8, Bn), 256 thr. Also inits out = clf_b.
// =====================================================================
__global__ __launch_bounds__(256, 4)
void scores_kernel(const float* __restrict__ q,
                   const float* __restrict__ k,
                   const float* __restrict__ asp,
                   const float* __restrict__ bias_m,
                   const int*   __restrict__ src_mask,
                   const float* __restrict__ short_mask,
                   const float* __restrict__ Wx_w,
                   const float* __restrict__ clf_b,
                   float* __restrict__ hs0,
                   float* __restrict__ hsw,
                   float* __restrict__ out) {
    int it = blockIdx.x, b = blockIdx.y;
    __shared__ float kt[Ln][21];
    __shared__ float addv[Ln];
    __shared__ float qs[8][20];
    __shared__ float sasp[DK];
    __shared__ int   msk[Ln];
    int t = threadIdx.x, w = t >> 5, lane = t & 31;
    int i = it * 8 + w;

    if (it == 0 && t < 3) out[b * 3 + t] = clf_b[t];

    if (t < DK) sasp[t] = asp[b * DK + t];
    msk[t] = src_mask[b * Ln + t];

    float ws[5];
    #pragma unroll
    for (int h = 0; h < 5; h++) {
        float s = 0.f;
        #pragma unroll
        for (int kk = 0; kk < 5; kk++) s += Wx_w[h * 5 + kk];
        ws[h] = s;
    }

    const float* srow = short_mask + ((long long)b * Ln + i) * Ln;
    float smr[8];
    #pragma unroll
    for (int jj = 0; jj < 8; jj++) smr[jj] = srow[lane + jj * 32];

    float h0acc[8] = {0.f,0.f,0.f,0.f,0.f,0.f,0.f,0.f};
    float hwacc[8] = {0.f,0.f,0.f,0.f,0.f,0.f,0.f,0.f};
    const float rsd = 0.22360679774997896f;
    float biasv = bias_m[0];

    for (int h = 0; h < Hh; h++) {
        __syncthreads();
        {
            const float4* kr = reinterpret_cast<const float4*>(
                k + ((long long)b * Ln + t) * ATT + h * DK);
            #pragma unroll
            for (int f = 0; f < 5; f++) {
                float4 v = kr[f];
                kt[t][f * 4 + 0] = v.x;
                kt[t][f * 4 + 1] = v.y;
                kt[t][f * 4 + 2] = v.z;
                kt[t][f * 4 + 3] = v.w;
            }
        }
        if (t < 160) {
            int r = t / 20, d = t % 20;
            qs[r][d] = q[((long long)b * Ln + it * 8 + r) * ATT + h * DK + d];
        }
        __syncthreads();
        {
            float s = 0.f;
            #pragma unroll
            for (int d = 0; d < DK; d++) s += sasp[d] * kt[t][d];
            addv[t] = tanhf(s + biasv);
        }
        __syncthreads();

        float sc[8] = {0.f,0.f,0.f,0.f,0.f,0.f,0.f,0.f};
        #pragma unroll
        for (int d = 0; d < DK; d++) {
            float qd = qs[w][d];
            #pragma unroll
            for (int jj = 0; jj < 8; jj++)
                sc[jj] += qd * kt[lane + jj * 32][d];
        }
        float mx = -3.4e38f;
        #pragma unroll
        for (int jj = 0; jj < 8; jj++) {
            int j = lane + jj * 32;
            float v = sc[jj] * rsd + addv[j];
            if (msk[j] == 0) v = -1e9f;
            v += smr[jj];
            sc[jj] = v;
            mx = fmaxf(mx, v);
        }
        #pragma unroll
        for (int o = 16; o > 0; o >>= 1) mx = fmaxf(mx, __shfl_xor_sync(0xffffffffu, mx, o));
        float sum = 0.f;
        #pragma unroll
        for (int jj = 0; jj < 8; jj++) { sc[jj] = expf(sc[jj] - mx); sum += sc[jj]; }
        #pragma unroll
        for (int o = 16; o > 0; o >>= 1) sum += __shfl_xor_sync(0xffffffffu, sum, o);
        float invs = 1.f / sum;
        float wsh = ws[h];
        #pragma unroll
        for (int jj = 0; jj < 8; jj++) {
            float a = sc[jj] * invs;
            h0acc[jj] += a;
            hwacc[jj] += a * wsh;
        }
    }
    float* r0 = hs0 + ((long long)b * Ln + i) * Ln;
    float* rw = hsw + ((long long)b * Ln + i) * Ln;
    #pragma unroll
    for (int jj = 0; jj < 8; jj++) {
        r0[lane + jj * 32] = h0acc[jj] * 0.2f;
        rw[lane + jj * 32] = hwacc[jj];
    }
}

// =====================================================================
// 4. Fused GCN layer, BM=32, grid (8,1,32)=256 CTAs, 320 threads.
//    mode 0: A = hs0 (pre-scaled); writes go, sg1, sg2.
//    mode 1: A = 0.2*(hsw + sbb + sg1[j] + sg2[i]); fused pool + classifier.
// =====================================================================
__global__ __launch_bounds__(320, 3)
void gcn_kernel(const float* __restrict__ Asrc,
                const float* __restrict__ Bsrc,
                const float* __restrict__ W_w,
                const float* __restrict__ W_b,
                const float* __restrict__ sg1,
                const float* __restrict__ sg2,
                const float* __restrict__ Wx_w,
                const float* __restrict__ Wx_b,
                const float* __restrict__ amask,
                const float* __restrict__ clf_w,
                float* __restrict__ outC,
                float* __restrict__ sg1o,
                float* __restrict__ sg2o,
                float* __restrict__ out,
                int mode) {
    __shared__ __align__(16) float As[2][16][36];
    __shared__ __align__(16) float Bs[2][16][104];
    __shared__ __align__(16) float AxS[33][101];
    __shared__ float smask[32];
    __shared__ float swn;

    int b = blockIdx.z;
    int m0 = blockIdx.x * 32;
    int tid = threadIdx.x;
    int tx = tid % 20, ty = tid / 20;      // ty 0..15 -> 2 rows
    int tx5 = tx * 5, ty2 = ty * 2;

    const float* Ab = Asrc + (long long)b * 65536;
    const float* Bb = Bsrc + (long long)b * (Ln * ATT);

    float sbb = 0.f;
    if (mode == 1) {
        #pragma unroll
        for (int kk2 = 0; kk2 < 5; kk2++) sbb += Wx_b[kk2];
        if (tid < 32) smask[tid] = amask[b * Ln + m0 + tid];
        if (tid >= 32 && tid < 64) {
            // full mask sum for 1/wn via one warp
            int lane = tid - 32;
            float s = 0.f;
            for (int x = lane; x < Ln; x += 32) s += amask[b * Ln + x];
            #pragma unroll
            for (int o = 16; o > 0; o >>= 1) s += __shfl_xor_sync(0xffffffffu, s, o);
            if (lane == 0) swn = 1.f / s;
        }
    }

    bool aok = (tid < 128);
    int ar = tid >> 2, ac = (tid & 3) << 2;      // 32 rows x 16 k / 4
    int b0r = tid / 25, b0c = (tid % 25) * 4;    // 16x100 = 400 f4
    int bi1 = tid + 320;
    bool b1ok = (bi1 < 400);
    int b1r = bi1 / 25, b1c = (bi1 % 25) * 4;

    float acc[2][5];
    #pragma unroll
    for (int i = 0; i < 2; i++)
        #pragma unroll
        for (int j = 0; j < 5; j++) acc[i][j] = 0.f;

    float4 aR = make_float4(0.f,0.f,0.f,0.f);
    float4 bR0 = aR, bR1 = aR;

    float sg2v = 0.f;
    if (mode == 1 && aok) sg2v = sg2[b * 256 + m0 + ar];

    #define LOAD_A(k0)                                                          \
        do {                                                                    \
            float4 v_ = *reinterpret_cast<const float4*>(                       \
                Ab + (long long)(m0 + ar) * 256 + (k0) + ac);                   \
            if (mode == 0) {                                                    \
                aR = v_;                                                        \
            } else {                                                            \
                float4 s1_ = *reinterpret_cast<const float4*>(sg1 + b * 256 + (k0) + ac); \
                float c_ = sbb + sg2v;                                          \
                aR.x = 0.2f * (v_.x + c_ + s1_.x);                              \
                aR.y = 0.2f * (v_.y + c_ + s1_.y);                              \
                aR.z = 0.2f * (v_.z + c_ + s1_.z);                              \
                aR.w = 0.2f * (v_.w + c_ + s1_.w);                              \
            }                                                                   \
        } while (0)

    if (aok) LOAD_A(0);
    bR0 = *reinterpret_cast<const float4*>(Bb + (long long)b0r * ATT + b0c);
    if (b1ok) bR1 = *reinterpret_cast<const float4*>(Bb + (long long)b1r * ATT + b1c);

    int s = 0;
    for (int t = 0; t < 16; t++) {
        if (aok) {
            As[s][ac + 0][ar] = aR.x;
            As[s][ac + 1][ar] = aR.y;
            As[s][ac + 2][ar] = aR.z;
            As[s][ac + 3][ar] = aR.w;
        }
        *reinterpret_cast<float4*>(&Bs[s][b0r][b0c]) = bR0;
        if (b1ok) *reinterpret_cast<float4*>(&Bs[s][b1r][b1c]) = bR1;
        __syncthreads();
        if (t + 1 < 16) {
            int k0 = (t + 1) * 16;
            if (aok) LOAD_A(k0);
            bR0 = *reinterpret_cast<const float4*>(Bb + (long long)(k0 + b0r) * ATT + b0c);
            if (b1ok) bR1 = *reinterpret_cast<const float4*>(Bb + (long long)(k0 + b1r) * ATT + b1c);
        }
        #pragma unroll
        for (int kk = 0; kk < 16; kk++) {
            float a0 = As[s][kk][ty2 + 0];
            float a1 = As[s][kk][ty2 + 1];
            float b0 = Bs[s][kk][tx5 + 0];
            float b1 = Bs[s][kk][tx5 + 1];
            float b2 = Bs[s][kk][tx5 + 2];
            float b3 = Bs[s][kk][tx5 + 3];
            float b4 = Bs[s][kk][tx5 + 4];
            acc[0][0] += a0*b0; acc[0][1] += a0*b1; acc[0][2] += a0*b2; acc[0][3] += a0*b3; acc[0][4] += a0*b4;
            acc[1][0] += a1*b0; acc[1][1] += a1*b1; acc[1][2] += a1*b2; acc[1][3] += a1*b3; acc[1][4] += a1*b4;
        }
        s ^= 1;
        __syncthreads();
    }
    #undef LOAD_A

    // stash Ax tile
    #pragma unroll
    for (int i = 0; i < 2; i++)
        #pragma unroll
        for (int j = 0; j < 5; j++)
            AxS[ty2 + i][tx5 + j] = acc[i][j];

    // second GEMM: acc2 = AxS @ W_w (K=100)
    float acc2[2][5];
    #pragma unroll
    for (int i = 0; i < 2; i++)
        #pragma unroll
        for (int j = 0; j < 5; j++) acc2[i][j] = 0.f;

    for (int k2 = 0; k2 < ATT; k2 += 16) {
        int kmax = ATT - k2; if (kmax > 16) kmax = 16;
        __syncthreads();
        for (int i = tid; i < 400; i += 320) {
            int row = i / 25, c4 = (i % 25) * 4;
            float4 v = make_float4(0.f,0.f,0.f,0.f);
            if (row < kmax) v = *reinterpret_cast<const float4*>(W_w + (long long)(k2 + row) * ATT + c4);
            *reinterpret_cast<float4*>(&Bs[0][row][c4]) = v;
        }
        __syncthreads();
        for (int kk = 0; kk < kmax; kk++) {
            float a0 = AxS[ty2 + 0][k2 + kk];
            float a1 = AxS[ty2 + 1][k2 + kk];
            float b0 = Bs[0][kk][tx5 + 0];
            float b1 = Bs[0][kk][tx5 + 1];
            float b2 = Bs[0][kk][tx5 + 2];
            float b3 = Bs[0][kk][tx5 + 3];
            float b4 = Bs[0][kk][tx5 + 4];
            acc2[0][0] += a0*b0; acc2[0][1] += a0*b1; acc2[0][2] += a0*b2; acc2[0][3] += a0*b3; acc2[0][4] += a0*b4;
            acc2[1][0] += a1*b0; acc2[1][1] += a1*b1; acc2[1][2] += a1*b2; acc2[1][3] += a1*b3; acc2[1][4] += a1*b4;
        }
    }

    float wb[5];
    #pragma unroll
    for (int j = 0; j < 5; j++) wb[j] = W_b[tx5 + j];

    if (mode == 0) {
        float w1r[5], w2r[5];
        #pragma unroll
        for (int j = 0; j < 5; j++) {
            float s1 = 0.f, s2 = 0.f;
            #pragma unroll
            for (int kk2 = 0; kk2 < 5; kk2++) {
                s1 += Wx_w[(5 + tx5 + j) * 5 + kk2];
                s2 += Wx_w[(105 + tx5 + j) * 5 + kk2];
            }
            w1r[j] = s1; w2r[j] = s2;
        }
        float p1[2] = {0.f,0.f}, p2[2] = {0.f,0.f};
        #pragma unroll
        for (int i = 0; i < 2; i++) {
            int gm = m0 + ty2 + i;
            float* crow = outC + ((long long)b * Ln + gm) * ATT;
            #pragma unroll
            for (int j = 0; j < 5; j++) {
                float v = fmaxf(acc2[i][j] + wb[j], 0.f);
                crow[tx5 + j] = v;
                p1[i] += v * w1r[j];
                p2[i] += v * w2r[j];
            }
        }
        __syncthreads();
        #pragma unroll
        for (int i = 0; i < 2; i++) {
            AxS[ty2 + i][tx]      = p1[i];
            AxS[ty2 + i][20 + tx] = p2[i];
        }
        __syncthreads();
        if (tid < 32) {
            float s1 = 0.f, s2 = 0.f;
            #pragma unroll
            for (int xx = 0; xx < 20; xx++) { s1 += AxS[tid][xx]; s2 += AxS[tid][20 + xx]; }
            sg1o[b * 256 + m0 + tid] = s1;
            sg2o[b * 256 + m0 + tid] = s2;
        }
    } else {
        // fused masked pool + classifier
        float pv[5] = {0.f,0.f,0.f,0.f,0.f};
        #pragma unroll
        for (int i = 0; i < 2; i++) {
            float m = smask[ty2 + i];
            #pragma unroll
            for (int j = 0; j < 5; j++)
                pv[j] += fmaxf(acc2[i][j] + wb[j], 0.f) * m;
        }
        __syncthreads();
        #pragma unroll
        for (int j = 0; j < 5; j++) AxS[ty][tx5 + j] = pv[j];
        __syncthreads();
        if (tid < ATT) {
            float s2 = 0.f;
            #pragma unroll
            for (int r = 0; r < 16; r++) s2 += AxS[r][tid];
            AxS[32][tid] = s2;
        }
        __syncthreads();
        if (tid < 3) {
            float s2 = 0.f;
            for (int c = 0; c < ATT; c++) s2 += AxS[32][c] * clf_w[c * 3 + tid];
            atomicAdd(out + b * 3 + tid, s2 * swn);
        }
    }
}

// ---------------- launch --------------------------------------------------
extern "C" void kernel_launch(void* const* d_in, const int* in_sizes, int n_in,
                              void* d_out, int out_size) {
    const float* seq     = (const float*)d_in[0];
    const int*   srcm    = (const int*)  d_in[1];
    const float* amask   = (const float*)d_in[2];
    const float* shortm  = (const float*)d_in[3];
    const float* ln_a    = (const float*)d_in[4];
    const float* ln_b    = (const float*)d_in[5];
    const float* Wxx_w   = (const float*)d_in[6];
    const float* Wxx_b   = (const float*)d_in[7];
    const float* q_w     = (const float*)d_in[8];
    const float* q_b     = (const float*)d_in[9];
    const float* k_w     = (const float*)d_in[10];
    const float* k_b     = (const float*)d_in[11];
    const float* dense_w = (const float*)d_in[12];
    const float* dense_b = (const float*)d_in[13];
    const float* bias_m  = (const float*)d_in[14];
    const float* W_w     = (const float*)d_in[15];
    const float* W_b     = (const float*)d_in[16];
    const float* Wx_w    = (const float*)d_in[17];
    const float* Wx_b    = (const float*)d_in[18];
    const float* clf_w   = (const float*)d_in[19];
    const float* clf_b   = (const float*)d_in[20];
    float* out = (float*)d_out;

    float* S = nullptr;
    cudaGetSymbolAddress((void**)&S, d_scratch);
    float* g     = S + OFF_G;
    float* q     = S + OFF_Q;
    float* k     = S + OFF_K;
    float* go    = S + OFF_GO;
    float* hs0   = S + OFF_HS0;
    float* hsw   = S + OFF_HSW;
    float* asp   = S + OFF_ASP;
    float* sg1   = S + OFF_SG1;
    float* sg2   = S + OFF_SG2;

    // 1. fused layernorm + g GEMM
    lng_kernel<<<NROW / 32, 320>>>(seq, ln_a, ln_b, Wxx_w, Wxx_b, g);
    // 2. q/k projections + aspect pooling
    qkaspect_kernel<<<288, 320>>>(g, q_w, q_b, k_w, k_b,
                                  amask, dense_w, dense_b, q, k, asp);
    // 3. scores + softmax -> hs0, hsw (adj never materialized); inits out
    scores_kernel<<<dim3(Ln / 8, Bn), 256>>>(q, k, asp, bias_m, srcm, shortm,
                                             Wx_w, clf_b, hs0, hsw, out);
    // 4. GCN layer 0
    gcn_kernel<<<dim3(8, 1, Bn), 320>>>(hs0, g, W_w, W_b,
                                        nullptr, nullptr, Wx_w, Wx_b,
                                        amask, clf_w,
                                        go, sg1, sg2, out, 0);
    // 5. GCN layer 1 + fused classifier
    gcn_kernel<<<dim3(8, 1, Bn), 320>>>(hsw, go, W_w, W_b,
                                        sg1, sg2, Wx_w, Wx_b,
                                        amask, clf_w,
                                        go, nullptr, nullptr, out, 1);
}